// round 2
// baseline (speedup 1.0000x reference)
#include <cuda_runtime.h>

// BranchRoute: score = sigmoid(x @ gate_w + gate_b); mask_i = score_i > 0.5
// out = concat(x*m0, x*m1, x*(m0+m1)), each [N, D] fp32.
// sigmoid(z) > 0.5 <=> z > 0, so only the dot-product sign matters.
//
// R2 changes vs R1 (86.5us, occ 35%, DRAM 73%):
//  - drop the 32-reg gate_w register cache; gate_w (32KB) lives in L1,
//    reloaded per row via __ldg (hidden L1 hits). regs 76 -> ~48.
//  - __launch_bounds__(256, 5): 5 blocks/SM -> 40 warps -> enough read MLP
//    to cover the BW*latency product (~16KB/SM outstanding needed).
//  - __ldcs on x, __stcs on outputs (no-reuse streaming hints).

#define THREADS 256
#define DIM 4096

__global__ void __launch_bounds__(THREADS, 5)
branch_route_kernel(const float* __restrict__ x,
                    const float* __restrict__ gw,   // [D, 2]
                    const float* __restrict__ gb,   // [2]
                    float* __restrict__ out,        // [3, N, D]
                    int N)
{
    const int t = threadIdx.x;
    const float2* __restrict__ gwv = (const float2*)gw;

    const float b0 = gb[0];
    const float b1 = gb[1];

    __shared__ float2 red[2][8];   // [parity][warp] partial (s0, s1)

    float* __restrict__ o0 = out;
    float* __restrict__ o1 = out + (size_t)N * DIM;
    float* __restrict__ oc = out + (size_t)2 * N * DIM;

    int parity = 0;
    for (int row = blockIdx.x; row < N; row += gridDim.x, parity ^= 1) {
        const float4* xr = (const float4*)(x + (size_t)row * DIM);

        // Load the row chunk (coalesced float4, streaming), keep in registers.
        float4 v[4];
#pragma unroll
        for (int c = 0; c < 4; c++) v[c] = __ldcs(&xr[c * 256 + t]);

        // Partial dots for both gate columns; gate_w pairs come from L1.
        float s0 = 0.f, s1 = 0.f;
#pragma unroll
        for (int c = 0; c < 4; c++) {
            const int col = c * 1024 + t * 4;
            float2 w0 = __ldg(&gwv[col + 0]);
            float2 w1 = __ldg(&gwv[col + 1]);
            float2 w2 = __ldg(&gwv[col + 2]);
            float2 w3 = __ldg(&gwv[col + 3]);
            s0 = fmaf(v[c].x, w0.x, s0);  s1 = fmaf(v[c].x, w0.y, s1);
            s0 = fmaf(v[c].y, w1.x, s0);  s1 = fmaf(v[c].y, w1.y, s1);
            s0 = fmaf(v[c].z, w2.x, s0);  s1 = fmaf(v[c].z, w2.y, s1);
            s0 = fmaf(v[c].w, w3.x, s0);  s1 = fmaf(v[c].w, w3.y, s1);
        }

        // Warp butterfly reduce.
#pragma unroll
        for (int o = 16; o > 0; o >>= 1) {
            s0 += __shfl_xor_sync(0xffffffffu, s0, o);
            s1 += __shfl_xor_sync(0xffffffffu, s1, o);
        }
        if ((t & 31) == 0) red[parity][t >> 5] = make_float2(s0, s1);
        __syncthreads();   // single barrier per row (double-buffered shared)

        float d0 = b0, d1 = b1;
#pragma unroll
        for (int k = 0; k < 8; k++) {
            d0 += red[parity][k].x;
            d1 += red[parity][k].y;
        }

        const float f0 = d0 > 0.f ? 1.f : 0.f;
        const float f1 = d1 > 0.f ? 1.f : 0.f;
        const float fc = f0 + f1;

        const size_t base = (size_t)row * (DIM / 4);
        float4* __restrict__ p0 = (float4*)o0 + base;
        float4* __restrict__ p1 = (float4*)o1 + base;
        float4* __restrict__ pc = (float4*)oc + base;

#pragma unroll
        for (int c = 0; c < 4; c++) {
            const int idx = c * 256 + t;
            float4 a, b, s;
            a.x = f0 * v[c].x; a.y = f0 * v[c].y; a.z = f0 * v[c].z; a.w = f0 * v[c].w;
            b.x = f1 * v[c].x; b.y = f1 * v[c].y; b.z = f1 * v[c].z; b.w = f1 * v[c].w;
            s.x = fc * v[c].x; s.y = fc * v[c].y; s.z = fc * v[c].z; s.w = fc * v[c].w;
            __stcs(&p0[idx], a);
            __stcs(&p1[idx], b);
            __stcs(&pc[idx], s);
        }
    }
}

extern "C" void kernel_launch(void* const* d_in, const int* in_sizes, int n_in,
                              void* d_out, int out_size)
{
    const float* x  = (const float*)d_in[0];
    const float* gw = (const float*)d_in[1];
    const float* gb = (const float*)d_in[2];
    float* out = (float*)d_out;

    const int N = in_sizes[0] / DIM;   // 8192

    const int grid = 148 * 8;          // persistent-ish; blocks loop over rows
    branch_route_kernel<<<grid, THREADS>>>(x, gw, gb, out, N);
}